// round 8
// baseline (speedup 1.0000x reference)
#include <cuda_runtime.h>
#include <cuda_bf16.h>
#include <cstdint>

#define BATCH    16
#define NPTS     2048
#define NPOINT   512
#define NSAMPLE  32
#define DFEAT    64
#define CIN1     67
#define NTOT     (BATCH * NSAMPLE * NPOINT)   /* 262144 */
#define GEMM_GRID (NTOT / 128)                /* 2048 */

// ---------------------------------------------------------------------------
// Static device scratch (no allocation anywhere)
// ---------------------------------------------------------------------------
__device__ float g_ptsT[BATCH * NPTS * DFEAT];
__device__ float g_newxyz[BATCH * NPOINT * 3];
__device__ int   g_gidx[BATCH * NPOINT * NSAMPLE];
__device__ float g_x [(size_t)CIN1 * NTOT];
__device__ float g_y1[(size_t)64   * NTOT];
__device__ float g_y2[(size_t)64   * NTOT];
__device__ float g_y3[(size_t)128  * NTOT];
__device__ float g_pS[(size_t)128 * GEMM_GRID];
__device__ float g_pQ[(size_t)128 * GEMM_GRID];
__device__ float g_scale[3][128];
__device__ float g_shift[3][128];

// ---------------------------------------------------------------------------
// K0: transpose points (B,64,2048) -> (B,2048,64)
// ---------------------------------------------------------------------------
__global__ void __launch_bounds__(256) transpose_kernel(const float* __restrict__ pts) {
    __shared__ float tile[32][33];
    int b = blockIdx.z, c0 = blockIdx.y * 32, n0 = blockIdx.x * 32;
    int tx = threadIdx.x, ty = threadIdx.y;
    #pragma unroll
    for (int i = ty; i < 32; i += 8)
        tile[i][tx] = pts[((size_t)b * DFEAT + c0 + i) * NPTS + n0 + tx];
    __syncthreads();
    #pragma unroll
    for (int i = ty; i < 32; i += 8)
        g_ptsT[((size_t)b * NPTS + n0 + i) * DFEAT + c0 + tx] = tile[tx][i];
}

// ---------------------------------------------------------------------------
// K1: farthest point sampling. One CTA per batch. Writes new_xyz to d_out.
// ---------------------------------------------------------------------------
__global__ void __launch_bounds__(256) fps_kernel(const float* __restrict__ xyz,
                                                  float* __restrict__ out) {
    __shared__ float sx[NPTS], sy[NPTS], sz[NPTS];
    __shared__ int farlist[NPOINT];
    __shared__ unsigned long long wkey[2][8];
    int b = blockIdx.x, tid = threadIdx.x;
    const float* base = xyz + (size_t)b * 3 * NPTS;
    for (int i = tid; i < NPTS; i += 256) {
        sx[i] = base[i]; sy[i] = base[NPTS + i]; sz[i] = base[2 * NPTS + i];
    }
    __syncthreads();
    float px[8], py[8], pz[8], dist[8];
    #pragma unroll
    for (int r = 0; r < 8; ++r) {
        int p = r * 256 + tid;
        px[r] = sx[p]; py[r] = sy[p]; pz[r] = sz[p];
        dist[r] = 1e10f;
    }
    int lane = tid & 31, warp = tid >> 5;
    int far = 0;
    for (int k = 0; k < NPOINT; ++k) {
        if (tid == 0) farlist[k] = far;
        float cx = sx[far], cy = sy[far], cz = sz[far];
        float best = -1.0f; int bidx = 0;
        #pragma unroll
        for (int r = 0; r < 8; ++r) {
            float dx = __fsub_rn(px[r], cx);
            float dy = __fsub_rn(py[r], cy);
            float dz = __fsub_rn(pz[r], cz);
            float d = __fadd_rn(__fadd_rn(__fmul_rn(dx, dx), __fmul_rn(dy, dy)),
                                __fmul_rn(dz, dz));
            float nd = fminf(dist[r], d);
            dist[r] = nd;
            if (nd > best) { best = nd; bidx = r * 256 + tid; }
        }
        unsigned long long key =
            ((unsigned long long)__float_as_uint(best) << 32) |
            (unsigned long long)(0xFFFFFFFFu - (unsigned)bidx);
        #pragma unroll
        for (int off = 16; off; off >>= 1) {
            unsigned long long o = __shfl_xor_sync(0xFFFFFFFFu, key, off);
            key = (o > key) ? o : key;
        }
        if (lane == 0) wkey[k & 1][warp] = key;
        __syncthreads();
        unsigned long long g = wkey[k & 1][0];
        #pragma unroll
        for (int w = 1; w < 8; ++w) {
            unsigned long long o = wkey[k & 1][w];
            g = (o > g) ? o : g;
        }
        far = (int)(0xFFFFFFFFu - (unsigned)(g & 0xFFFFFFFFull));
    }
    __syncthreads();
    for (int s = tid; s < NPOINT; s += 256) {
        int j = farlist[s];
        out[((size_t)b * 3 + 0) * NPOINT + s] = sx[j];
        out[((size_t)b * 3 + 1) * NPOINT + s] = sy[j];
        out[((size_t)b * 3 + 2) * NPOINT + s] = sz[j];
        g_newxyz[((size_t)b * NPOINT + s) * 3 + 0] = sx[j];
        g_newxyz[((size_t)b * NPOINT + s) * 3 + 1] = sy[j];
        g_newxyz[((size_t)b * NPOINT + s) * 3 + 2] = sz[j];
    }
}

// ---------------------------------------------------------------------------
// K2: ball query (8 query points per block). ballot + ordered ffs scan.
// ---------------------------------------------------------------------------
__global__ void __launch_bounds__(256) ballq_kernel(const float* __restrict__ xyz) {
    __shared__ float sx[NPTS], sy[NPTS], sz[NPTS];
    __shared__ float nx[8], ny[8], nz[8];
    __shared__ unsigned masks[8][64];
    int b = blockIdx.y, s0 = blockIdx.x * 8, tid = threadIdx.x;
    const float* base = xyz + (size_t)b * 3 * NPTS;
    for (int i = tid; i < NPTS; i += 256) {
        sx[i] = base[i]; sy[i] = base[NPTS + i]; sz[i] = base[2 * NPTS + i];
    }
    if (tid < 8) {
        const float* q = &g_newxyz[((size_t)b * NPOINT + s0 + tid) * 3];
        nx[tid] = q[0]; ny[tid] = q[1]; nz[tid] = q[2];
    }
    __syncthreads();
    const float R2 = (float)(0.2 * 0.2);   // f32(f64 0.04) matches weak-typed promotion
    int lane = tid & 31, warp = tid >> 5;
    for (int ss = 0; ss < 8; ++ss) {
        float qx = nx[ss], qy = ny[ss], qz = nz[ss];
        #pragma unroll
        for (int gi = 0; gi < 8; ++gi) {
            int g = warp * 8 + gi;
            int p = g * 32 + lane;
            float dx = __fsub_rn(sx[p], qx);
            float dy = __fsub_rn(sy[p], qy);
            float dz = __fsub_rn(sz[p], qz);
            float d = __fadd_rn(__fadd_rn(__fmul_rn(dx, dx), __fmul_rn(dy, dy)),
                                __fmul_rn(dz, dz));
            unsigned m = __ballot_sync(0xFFFFFFFFu, d <= R2);
            if (lane == 0) masks[ss][g] = m;
        }
    }
    __syncthreads();
    if (tid < 8) {
        int s = s0 + tid;
        int cnt = 0, first = 0;
        size_t ob = ((size_t)b * NPOINT + s) * NSAMPLE;
        for (int g = 0; g < 64 && cnt < NSAMPLE; ++g) {
            unsigned m = masks[tid][g];
            while (m && cnt < NSAMPLE) {
                int bit = __ffs(m) - 1;
                m &= m - 1;
                int id = g * 32 + bit;
                if (cnt == 0) first = id;
                g_gidx[ob + cnt] = id;
                ++cnt;
            }
        }
        for (; cnt < NSAMPLE; ++cnt) g_gidx[ob + cnt] = first;
    }
}

// ---------------------------------------------------------------------------
// K3: gather + concat -> x[c][n], n = b*16384 + k*512 + s
// ---------------------------------------------------------------------------
__global__ void __launch_bounds__(256) gather_kernel(const float* __restrict__ xyz) {
    int n = blockIdx.x * 256 + threadIdx.x;
    int b = n >> 14;
    int r = n & 16383;
    int k = r >> 9;
    int s = r & 511;
    int j = g_gidx[((size_t)b * NPOINT + s) * NSAMPLE + k];
    const float* q = &g_newxyz[((size_t)b * NPOINT + s) * 3];
    const float* xb = xyz + (size_t)b * 3 * NPTS;
    g_x[(size_t)0 * NTOT + n] = __fsub_rn(xb[j], q[0]);
    g_x[(size_t)1 * NTOT + n] = __fsub_rn(xb[NPTS + j], q[1]);
    g_x[(size_t)2 * NTOT + n] = __fsub_rn(xb[2 * NPTS + j], q[2]);
    const float4* prow = (const float4*)&g_ptsT[((size_t)b * NPTS + j) * DFEAT];
    #pragma unroll
    for (int c4 = 0; c4 < 16; ++c4) {
        float4 v = prow[c4];
        size_t o = (size_t)(3 + c4 * 4) * NTOT + n;
        g_x[o] = v.x;
        g_x[o + (size_t)NTOT] = v.y;
        g_x[o + 2 * (size_t)NTOT] = v.z;
        g_x[o + 3 * (size_t)NTOT] = v.w;
    }
}

// ---------------------------------------------------------------------------
// GEMM + bias, fused BN(prev)+ReLU on load, fused per-channel sum/sumsq.
// Block: 128 pixels x COUT channels, 256 threads = 16(n) x 16(o-groups).
// ---------------------------------------------------------------------------
template <int LAYER, int CIN, int COUT>
__global__ void __launch_bounds__(256) gemm_bn_kernel(const float* __restrict__ W,
                                                      const float* __restrict__ bias) {
    extern __shared__ float smem[];
    float* Xs = smem;                 // CIN * 128
    float* Ws = smem + CIN * 128;     // [c][o]
    constexpr int RO = COUT / 16;

    const float* X; float* Y; const float* sc = nullptr; const float* sh = nullptr;
    if constexpr (LAYER == 0)      { X = g_x;  Y = g_y1; }
    else if constexpr (LAYER == 1) { X = g_y1; Y = g_y2; sc = g_scale[0]; sh = g_shift[0]; }
    else                           { X = g_y2; Y = g_y3; sc = g_scale[1]; sh = g_shift[1]; }

    int tid = threadIdx.x, bx = blockIdx.x;
    int n0 = bx * 128;
    for (int i = tid; i < CIN * COUT; i += 256) {
        int o = i / CIN, c = i - o * CIN;
        Ws[c * COUT + o] = W[i];
    }
    for (int i = tid; i < CIN * 128; i += 256) {
        int c = i >> 7, nn = i & 127;
        float v = X[(size_t)c * NTOT + n0 + nn];
        if constexpr (LAYER > 0)
            v = fmaxf(fmaf(v, sc[c], sh[c]), 0.0f);
        Xs[i] = v;
    }
    __syncthreads();

    int nt = tid & 15, ot = tid >> 4;
    int nb = nt * 8, ob = ot * RO;
    float acc[8][RO];
    #pragma unroll
    for (int r = 0; r < 8; ++r)
        #pragma unroll
        for (int j = 0; j < RO; ++j) acc[r][j] = 0.0f;

    for (int c = 0; c < CIN; ++c) {
        float xv[8];
        *(float4*)&xv[0] = *(const float4*)&Xs[c * 128 + nb];
        *(float4*)&xv[4] = *(const float4*)&Xs[c * 128 + nb + 4];
        float wv[RO];
        #pragma unroll
        for (int j = 0; j < RO; j += 4)
            *(float4*)&wv[j] = *(const float4*)&Ws[c * COUT + ob + j];
        #pragma unroll
        for (int r = 0; r < 8; ++r)
            #pragma unroll
            for (int j = 0; j < RO; ++j)
                acc[r][j] = fmaf(xv[r], wv[j], acc[r][j]);
    }

    #pragma unroll
    for (int j = 0; j < RO; ++j) {
        float bb = bias[ob + j];
        float s = 0.0f, q = 0.0f;
        #pragma unroll
        for (int r = 0; r < 8; ++r) {
            float v = acc[r][j] + bb;
            acc[r][j] = v;
            s += v;
            q = fmaf(v, v, q);
        }
        float* yrow = &Y[(size_t)(ob + j) * NTOT + n0 + nb];
        *(float4*)&yrow[0] = *(float4*)&acc[0][j];  // note: acc[r][j] not contiguous; store scalar
        // (scalar stores below overwrite correctly; keep it simple & correct)
        #pragma unroll
        for (int r = 0; r < 8; ++r) yrow[r] = acc[r][j];
        #pragma unroll
        for (int off = 8; off; off >>= 1) {
            s += __shfl_xor_sync(0xFFFFFFFFu, s, off);
            q += __shfl_xor_sync(0xFFFFFFFFu, q, off);
        }
        if ((tid & 15) == 0) {
            g_pS[(size_t)(ob + j) * GEMM_GRID + bx] = s;
            g_pQ[(size_t)(ob + j) * GEMM_GRID + bx] = q;
        }
    }
}

// ---------------------------------------------------------------------------
// BN stats reduce: one block per channel.
// ---------------------------------------------------------------------------
template <int LAYER>
__global__ void __launch_bounds__(256) stats_kernel(const float* __restrict__ gamma,
                                                    const float* __restrict__ beta) {
    __shared__ float ss[256], qq[256];
    int c = blockIdx.x, tid = threadIdx.x;
    float s = 0.0f, q = 0.0f;
    for (int i = tid; i < GEMM_GRID; i += 256) {
        s += g_pS[(size_t)c * GEMM_GRID + i];
        q += g_pQ[(size_t)c * GEMM_GRID + i];
    }
    ss[tid] = s; qq[tid] = q;
    __syncthreads();
    for (int off = 128; off; off >>= 1) {
        if (tid < off) { ss[tid] += ss[tid + off]; qq[tid] += qq[tid + off]; }
        __syncthreads();
    }
    if (tid == 0) {
        float mean = ss[0] * (1.0f / NTOT);
        float var = qq[0] * (1.0f / NTOT) - mean * mean;
        float scl = gamma[c] * rsqrtf(var + 1e-5f);
        g_scale[LAYER][c] = scl;
        g_shift[LAYER][c] = beta[c] - mean * scl;
    }
}

// ---------------------------------------------------------------------------
// Final: BN(2)+ReLU+max over k. out feature at offset 24576, (b,c,s).
// ---------------------------------------------------------------------------
__global__ void __launch_bounds__(256) final_kernel(float* __restrict__ out) {
    int t = blockIdx.x * 256 + threadIdx.x;      // t = b*65536 + c*512 + s
    int s = t & 511;
    int c = (t >> 9) & 127;
    int b = t >> 16;
    float scl = g_scale[2][c], sft = g_shift[2][c];
    const float* y = &g_y3[(size_t)c * NTOT + (size_t)b * 16384 + s];
    float m = -1e30f;
    #pragma unroll
    for (int k = 0; k < 32; ++k)
        m = fmaxf(m, fmaf(y[(size_t)k * 512], scl, sft));
    out[24576 + t] = fmaxf(m, 0.0f);
}

// ---------------------------------------------------------------------------
// Launch
// ---------------------------------------------------------------------------
extern "C" void kernel_launch(void* const* d_in, const int* in_sizes, int n_in,
                              void* d_out, int out_size) {
    const float* xyz = (const float*)d_in[0];
    const float* pts = (const float*)d_in[1];
    const float* w0 = (const float*)d_in[2];
    const float* b0 = (const float*)d_in[3];
    const float* g0 = (const float*)d_in[4];
    const float* bt0 = (const float*)d_in[5];
    const float* w1 = (const float*)d_in[6];
    const float* b1 = (const float*)d_in[7];
    const float* g1 = (const float*)d_in[8];
    const float* bt1 = (const float*)d_in[9];
    const float* w2 = (const float*)d_in[10];
    const float* b2 = (const float*)d_in[11];
    const float* g2 = (const float*)d_in[12];
    const float* bt2 = (const float*)d_in[13];
    float* out = (float*)d_out;

    const int smem0 = (CIN1 * 128 + CIN1 * 64) * 4;   // 51456
    const int smem1 = (64 * 128 + 64 * 64) * 4;       // 49152
    const int smem2 = (64 * 128 + 64 * 128) * 4;      // 65536
    cudaFuncSetAttribute(gemm_bn_kernel<0, CIN1, 64>,
                         cudaFuncAttributeMaxDynamicSharedMemorySize, smem0);
    cudaFuncSetAttribute(gemm_bn_kernel<1, 64, 64>,
                         cudaFuncAttributeMaxDynamicSharedMemorySize, smem1);
    cudaFuncSetAttribute(gemm_bn_kernel<2, 64, 128>,
                         cudaFuncAttributeMaxDynamicSharedMemorySize, smem2);

    dim3 tb(32, 8);
    dim3 tg(NPTS / 32, DFEAT / 32, BATCH);
    transpose_kernel<<<tg, tb>>>(pts);
    fps_kernel<<<BATCH, 256>>>(xyz, out);
    ballq_kernel<<<dim3(NPOINT / 8, BATCH), 256>>>(xyz);
    gather_kernel<<<NTOT / 256, 256>>>(xyz);

    gemm_bn_kernel<0, CIN1, 64><<<GEMM_GRID, 256, smem0>>>(w0, b0);
    stats_kernel<0><<<64, 256>>>(g0, bt0);
    gemm_bn_kernel<1, 64, 64><<<GEMM_GRID, 256, smem1>>>(w1, b1);
    stats_kernel<1><<<64, 256>>>(g1, bt1);
    gemm_bn_kernel<2, 64, 128><<<GEMM_GRID, 256, smem2>>>(w2, b2);
    stats_kernel<2><<<128, 256>>>(g2, bt2);

    final_kernel<<<(BATCH * 128 * 512) / 256, 256>>>(out);
}